// round 9
// baseline (speedup 1.0000x reference)
#include <cuda_runtime.h>
#include <cuda_bf16.h>
#include <math.h>
#include <cstdint>

// Problem constants: N=100000, E=1600000, D_IN=128, D_H=128, D_OUT=64
#define NN 100000
#define EE 1600000
#define KDIM 128

// -------- device-global scratch (allocations are forbidden) --------
__device__ float g_bufA[(size_t)NN * 128];   // GEMM output G
__device__ float g_bufB[(size_t)NN * 128];   // post-aggregation activations (layer1)
__device__ int      g_cnt[NN];
__device__ int      g_rowptr[NN + 1];
__device__ int      g_wp[NN];
__device__ int      g_col[EE];
__device__ float    g_dinv[NN];
__device__ unsigned g_state[512];            // lookback scan state
// bf16 hi/lo weights, [N][K] row-major (K contiguous)  == W^T
__device__ __nv_bfloat16 g_W1hi[128 * 128];
__device__ __nv_bfloat16 g_W1lo[128 * 128];
__device__ __nv_bfloat16 g_W2hi[64 * 128];
__device__ __nv_bfloat16 g_W2lo[64 * 128];

// ================= small helpers =================
__device__ __forceinline__ uint32_t smem_u32(const void* p) {
    uint32_t a;
    asm("{ .reg .u64 t; cvta.to.shared.u64 t, %1; cvt.u32.u64 %0, t; }" : "=r"(a) : "l"(p));
    return a;
}
__device__ __forceinline__ void ldmatrix_x4(uint32_t& r0, uint32_t& r1, uint32_t& r2,
                                            uint32_t& r3, uint32_t addr) {
    asm volatile("ldmatrix.sync.aligned.m8n8.x4.shared.b16 {%0,%1,%2,%3}, [%4];"
                 : "=r"(r0), "=r"(r1), "=r"(r2), "=r"(r3) : "r"(addr));
}
__device__ __forceinline__ void ldmatrix_x2(uint32_t& r0, uint32_t& r1, uint32_t addr) {
    asm volatile("ldmatrix.sync.aligned.m8n8.x2.shared.b16 {%0,%1}, [%2];"
                 : "=r"(r0), "=r"(r1) : "r"(addr));
}
__device__ __forceinline__ void mma_bf16(float* d, const uint32_t* a, const uint32_t* b) {
    asm volatile(
        "mma.sync.aligned.m16n8k16.row.col.f32.bf16.bf16.f32 "
        "{%0,%1,%2,%3}, {%4,%5,%6,%7}, {%8,%9}, {%0,%1,%2,%3};"
        : "+f"(d[0]), "+f"(d[1]), "+f"(d[2]), "+f"(d[3])
        : "r"(a[0]), "r"(a[1]), "r"(a[2]), "r"(a[3]), "r"(b[0]), "r"(b[1]));
}

// ======== weight convert (both layers in one kernel): fp32 [K][N] -> hi/lo bf16 [N][K] ========
__global__ void k_convW_all(const float* __restrict__ W1, const float* __restrict__ W2) {
    int i = blockIdx.x * blockDim.x + threadIdx.x;
    if (i < 128 * 128) {
        int k = i / 128, nn = i % 128;
        float v = W1[i];
        __nv_bfloat16 h = __float2bfloat16(v);
        g_W1hi[nn * 128 + k] = h;
        g_W1lo[nn * 128 + k] = __float2bfloat16(v - __bfloat162float(h));
    } else if (i < 128 * 128 + 128 * 64) {
        int j = i - 128 * 128;
        int k = j / 64, nn = j % 64;
        float v = W2[j];
        __nv_bfloat16 h = __float2bfloat16(v);
        g_W2hi[nn * 128 + k] = h;
        g_W2lo[nn * 128 + k] = __float2bfloat16(v - __bfloat162float(h));
    }
}

// ================= CSR build =================
// counts + zero the scan state (state used only by k_scan, launched after)
__global__ void k_count(const int* __restrict__ dst, int e) {
    int i = blockIdx.x * blockDim.x + threadIdx.x;
    if (i < 512) g_state[i] = 0u;
    if (i < e) atomicAdd(&g_cnt[dst[i]], 1);
}

// single-pass exclusive scan (decoupled lookback), also emits dinv and rowptr[n]
__global__ void k_scan(int n, int nb) {
    __shared__ int sh[512];
    __shared__ int s_prev;
    const int tid = threadIdx.x;
    const int b = blockIdx.x;
    const int i = b * 512 + tid;
    int v = (i < n) ? g_cnt[i] : 0;
    if (i < n) g_dinv[i] = rsqrtf((float)v + 1.0f);   // self-loop folded in
    sh[tid] = v;
    __syncthreads();
#pragma unroll
    for (int off = 1; off < 512; off <<= 1) {
        int t = (tid >= off) ? sh[tid - off] : 0;
        __syncthreads();
        sh[tid] += t;
        __syncthreads();
    }
    const int incl = sh[tid];
    const int total = sh[511];

    if (tid == 0) {
        if (b == 0) {
            atomicExch(&g_state[0], (2u << 30) | (unsigned)total);
            s_prev = 0;
        } else {
            atomicExch(&g_state[b], (1u << 30) | (unsigned)total);
            int run = 0, p = b - 1;
            while (true) {
                unsigned s;
                do { s = atomicOr(&g_state[p], 0u); } while ((s >> 30) == 0u);
                run += (int)(s & 0x3FFFFFFFu);
                if ((s >> 30) == 2u) break;
                p--;
            }
            atomicExch(&g_state[b], (2u << 30) | (unsigned)(run + total));
            s_prev = run;
        }
    }
    __syncthreads();
    const int base = s_prev;
    if (i < n) {
        int ex = base + incl - v;
        g_rowptr[i] = ex;
        g_wp[i] = ex;
    }
    if (b == nb - 1 && tid == 511) g_rowptr[n] = base + total;
}

__global__ void k_fill(const int* __restrict__ src, const int* __restrict__ dst, int e) {
    int i = blockIdx.x * blockDim.x + threadIdx.x;
    if (i < e) {
        int d = dst[i];
        int pos = atomicAdd(&g_wp[d], 1);
        g_col[pos] = src[i];
    }
}

// ================= mma.sync GEMM: G = X @ W  (no scaling; dinv applied in agg) =================
// 3-term bf16 compensated: Ahi*Bhi + Ahi*Blo + Alo*Bhi, fp32 accumulate.
// CTA: 256 threads (8 warps), tile 128 x NCOL. Warp w: rows [w*16, w*16+16).
template <int NCOL>
__global__ void __launch_bounds__(256, 1)
k_gemm_mma(const float* __restrict__ X, const __nv_bfloat16* __restrict__ Bhi,
           const __nv_bfloat16* __restrict__ Blo, float* __restrict__ G, int n) {
    constexpr int K = 128;
    constexpr int PAD = 136;                 // halves per row (8 halves pad)
    constexpr int NT = NCOL / 8;             // n-tiles per warp
    constexpr int ABYTES = 128 * PAD * 2;    // 34816 per half
    constexpr int BBYTES = NCOL * PAD * 2;

    extern __shared__ char smem[];
    __nv_bfloat16* sAhi = (__nv_bfloat16*)(smem);
    __nv_bfloat16* sAlo = (__nv_bfloat16*)(smem + ABYTES);
    __nv_bfloat16* sBhi = (__nv_bfloat16*)(smem + 2 * ABYTES);
    __nv_bfloat16* sBlo = (__nv_bfloat16*)(smem + 2 * ABYTES + BBYTES);

    const int tid = threadIdx.x;
    const int wid = tid >> 5;
    const int lane = tid & 31;
    const int rowBase = blockIdx.x * 128;

    // ---- stage B (hi/lo) into padded smem, 16B chunks ----
    {
        const uint4* bh = (const uint4*)Bhi;
        const uint4* bl = (const uint4*)Blo;
        for (int c = tid; c < NCOL * 16; c += 256) {
            int r = c >> 4, c8 = c & 15;        // 8 halves per chunk
            uint4 vh = bh[c], vl = bl[c];
            *(uint4*)(&sBhi[r * PAD + c8 * 8]) = vh;
            *(uint4*)(&sBlo[r * PAD + c8 * 8]) = vl;
        }
    }

    // ---- stage A tile: 128 rows x 128 fp32 -> hi/lo bf16 ----
    for (int i = tid; i < 128 * 32; i += 256) {
        int r = i >> 5, c4 = i & 31;            // float4 index in row
        float4 v = make_float4(0.f, 0.f, 0.f, 0.f);
        int gr = rowBase + r;
        if (gr < n) v = ((const float4*)X)[(size_t)gr * 32 + c4];
        __nv_bfloat16 h0 = __float2bfloat16(v.x), h1 = __float2bfloat16(v.y);
        __nv_bfloat16 h2 = __float2bfloat16(v.z), h3 = __float2bfloat16(v.w);
        __nv_bfloat16 l0 = __float2bfloat16(v.x - __bfloat162float(h0));
        __nv_bfloat16 l1 = __float2bfloat16(v.y - __bfloat162float(h1));
        __nv_bfloat16 l2 = __float2bfloat16(v.z - __bfloat162float(h2));
        __nv_bfloat16 l3 = __float2bfloat16(v.w - __bfloat162float(h3));
        __nv_bfloat162* ph = (__nv_bfloat162*)&sAhi[r * PAD + c4 * 4];
        __nv_bfloat162* pl = (__nv_bfloat162*)&sAlo[r * PAD + c4 * 4];
        ph[0] = __nv_bfloat162(h0, h1); ph[1] = __nv_bfloat162(h2, h3);
        pl[0] = __nv_bfloat162(l0, l1); pl[1] = __nv_bfloat162(l2, l3);
    }
    __syncthreads();

    // ---- per-warp mma mainloop ----
    const int m0 = wid * 16;
    const uint32_t aRow = m0 + (lane & 15);
    const uint32_t aK = (lane >> 4) * 8;
    const uint32_t aHiAddr = smem_u32(&sAhi[aRow * PAD + aK]);
    const uint32_t aLoAddr = smem_u32(&sAlo[aRow * PAD + aK]);
    const uint32_t bRow = (lane & 7);
    const uint32_t bK = ((lane >> 3) & 1) * 8;
    const uint32_t bHiAddr = smem_u32(&sBhi[bRow * PAD + bK]);
    const uint32_t bLoAddr = smem_u32(&sBlo[bRow * PAD + bK]);

    float d[NT][4];
#pragma unroll
    for (int j = 0; j < NT; j++) { d[j][0] = 0.f; d[j][1] = 0.f; d[j][2] = 0.f; d[j][3] = 0.f; }

#pragma unroll
    for (int k0 = 0; k0 < K; k0 += 16) {
        uint32_t ahi[4], alo[4];
        ldmatrix_x4(ahi[0], ahi[1], ahi[2], ahi[3], aHiAddr + k0 * 2);
        ldmatrix_x4(alo[0], alo[1], alo[2], alo[3], aLoAddr + k0 * 2);
#pragma unroll
        for (int j = 0; j < NT; j++) {
            uint32_t bhi[2], blo[2];
            const uint32_t boff = (j * 8) * (PAD * 2) + k0 * 2;
            ldmatrix_x2(bhi[0], bhi[1], bHiAddr + boff);
            ldmatrix_x2(blo[0], blo[1], bLoAddr + boff);
            mma_bf16(d[j], ahi, bhi);
            mma_bf16(d[j], ahi, blo);
            mma_bf16(d[j], alo, bhi);
        }
    }

    // ---- epilogue: plain store ----
    const int r0 = rowBase + m0 + (lane >> 2);
    const int r1 = r0 + 8;
    const int cbase = (lane & 3) * 2;
#pragma unroll
    for (int j = 0; j < NT; j++) {
        int col = j * 8 + cbase;
        if (r0 < n)
            *(float2*)(G + (size_t)r0 * NCOL + col) = make_float2(d[j][0], d[j][1]);
        if (r1 < n)
            *(float2*)(G + (size_t)r1 * NCOL + col) = make_float2(d[j][2], d[j][3]);
    }
}

// ================= aggregation: one warp per destination node =================
// out[d] = act( dinv[d] * (sum_s dinv[s]*G[s] + dinv[d]*G[d]) + bias )
template <int D, bool LAYER2>
__global__ void k_agg(const float* __restrict__ G, const float* __restrict__ bias,
                      float* __restrict__ out, int n) {
    const int warp = (blockIdx.x * blockDim.x + threadIdx.x) >> 5;
    const int lane = threadIdx.x & 31;
    if (warp >= n) return;
    constexpr int VPL = D / 32;

    const float dv = g_dinv[warp];
    float acc[VPL];
    {   // self loop: dinv[d] * G[d]
        const float* row = G + (size_t)warp * D;
        if (VPL == 4) {
            float4 v = ((const float4*)row)[lane];
            acc[0] = dv * v.x; acc[1] = dv * v.y; acc[2] = dv * v.z; acc[3] = dv * v.w;
        } else {
            float2 v = ((const float2*)row)[lane];
            acc[0] = dv * v.x; acc[1] = dv * v.y;
        }
    }

    int r = g_rowptr[warp];
    const int end = g_rowptr[warp + 1];

    // unroll-8 for memory-level parallelism
    for (; r + 7 < end; r += 8) {
        int s[8];
#pragma unroll
        for (int u = 0; u < 8; u++) s[u] = g_col[r + u];
        if (VPL == 4) {
            float4 v[8];
#pragma unroll
            for (int u = 0; u < 8; u++) v[u] = ((const float4*)(G + (size_t)s[u] * D))[lane];
#pragma unroll
            for (int u = 0; u < 8; u++) {
                float w = g_dinv[s[u]];
                acc[0] += w * v[u].x; acc[1] += w * v[u].y;
                acc[2] += w * v[u].z; acc[3] += w * v[u].w;
            }
        } else {
            float2 v[8];
#pragma unroll
            for (int u = 0; u < 8; u++) v[u] = ((const float2*)(G + (size_t)s[u] * D))[lane];
#pragma unroll
            for (int u = 0; u < 8; u++) {
                float w = g_dinv[s[u]];
                acc[0] += w * v[u].x; acc[1] += w * v[u].y;
            }
        }
    }
    for (; r < end; r++) {
        int s = g_col[r];
        float w = g_dinv[s];
        if (VPL == 4) {
            float4 v = ((const float4*)(G + (size_t)s * D))[lane];
            acc[0] += w * v.x; acc[1] += w * v.y; acc[2] += w * v.z; acc[3] += w * v.w;
        } else {
            float2 v = ((const float2*)(G + (size_t)s * D))[lane];
            acc[0] += w * v.x; acc[1] += w * v.y;
        }
    }

    if (!LAYER2) {
        const float alpha = 1.6732632423543772f;
        const float scale = 1.0507009873554805f;
        float o[VPL];
#pragma unroll
        for (int v = 0; v < VPL; v++) {
            float x = dv * acc[v] + bias[lane * VPL + v];
            o[v] = scale * (x > 0.f ? x : alpha * (expf(x) - 1.f));
        }
        if (VPL == 4) {
            ((float4*)(out + (size_t)warp * D))[lane] = make_float4(o[0], o[1], o[2], o[3]);
        }
    } else {
        float v0 = dv * acc[0] + bias[lane * 2];
        float v1 = dv * acc[1] + bias[lane * 2 + 1];
        float m = fmaxf(v0, v1);
#pragma unroll
        for (int o = 16; o >= 1; o >>= 1) m = fmaxf(m, __shfl_xor_sync(0xffffffffu, m, o));
        float s = expf(v0 - m) + expf(v1 - m);
#pragma unroll
        for (int o = 16; o >= 1; o >>= 1) s += __shfl_xor_sync(0xffffffffu, s, o);
        float l = logf(s);
        ((float2*)(out + (size_t)warp * D))[lane] = make_float2(v0 - m - l, v1 - m - l);
    }
}

// ================= launch =================
extern "C" void kernel_launch(void* const* d_in, const int* in_sizes, int n_in,
                              void* d_out, int out_size) {
    const float* x  = (const float*)d_in[0];
    const int*   ei = (const int*)d_in[1];
    const float* W1 = (const float*)d_in[2];
    const float* b1 = (const float*)d_in[3];
    const float* W2 = (const float*)d_in[4];
    const float* b2 = (const float*)d_in[5];
    float* out = (float*)d_out;

    const int n = in_sizes[0] / KDIM;   // 100000
    const int e = in_sizes[1] / 2;      // 1600000
    const int* src = ei;
    const int* dst = ei + e;

    float *pA, *pB;
    int* pCnt;
    __nv_bfloat16 *w1h, *w1l, *w2h, *w2l;
    cudaGetSymbolAddress((void**)&pA, g_bufA);
    cudaGetSymbolAddress((void**)&pB, g_bufB);
    cudaGetSymbolAddress((void**)&pCnt, g_cnt);
    cudaGetSymbolAddress((void**)&w1h, g_W1hi);
    cudaGetSymbolAddress((void**)&w1l, g_W1lo);
    cudaGetSymbolAddress((void**)&w2h, g_W2hi);
    cudaGetSymbolAddress((void**)&w2l, g_W2lo);

    const int nb = (n + 511) / 512;     // 196 blocks, all co-resident (lookback safe)

    // 1) weights (independent of CSR)
    k_convW_all<<<(128 * 128 + 128 * 64 + 255) / 256, 256>>>(W1, W2);

    // 2) CSR + dinv (memset node + 3 kernels)
    cudaMemsetAsync(pCnt, 0, (size_t)n * sizeof(int));
    k_count<<<(e + 255) / 256, 256>>>(dst, e);
    k_scan<<<nb, 512>>>(n, nb);
    k_fill<<<(e + 255) / 256, 256>>>(src, dst, e);

    // 3) GEMMs + aggregations
    constexpr int SM1 = 2 * (128 * 136 * 2) + 2 * (128 * 136 * 2);  // 139264
    constexpr int SM2 = 2 * (128 * 136 * 2) + 2 * (64 * 136 * 2);   // 104448
    cudaFuncSetAttribute(k_gemm_mma<128>, cudaFuncAttributeMaxDynamicSharedMemorySize, SM1);
    cudaFuncSetAttribute(k_gemm_mma<64>,  cudaFuncAttributeMaxDynamicSharedMemorySize, SM2);

    const int gemm_grid = (n + 127) / 128;   // 782
    const int agg_grid = (n * 32 + 255) / 256;

    k_gemm_mma<128><<<gemm_grid, 256, SM1>>>(x, w1h, w1l, pA, n);
    k_agg<128, false><<<agg_grid, 256>>>(pA, b1, pB, n);
    k_gemm_mma<64><<<gemm_grid, 256, SM2>>>(pB, w2h, w2l, pA, n);
    k_agg<64, true><<<agg_grid, 256>>>(pA, b2, out, n);
}

// round 10
// speedup vs baseline: 1.3989x; 1.3989x over previous
#include <cuda_runtime.h>
#include <cuda_bf16.h>
#include <math.h>
#include <cstdint>

// Problem constants: N=100000, E=1600000, D_IN=128, D_H=128, D_OUT=64
#define NN 100000
#define EE 1600000
#define KDIM 128

// -------- device-global scratch (allocations are forbidden) --------
__device__ float g_bufA[(size_t)NN * 128];   // GEMM output G
__device__ float g_bufB[(size_t)NN * 128];   // post-aggregation activations (layer1)
__device__ int      g_cnt[NN];
__device__ int      g_rowptr[NN + 1];
__device__ int      g_wp[NN];
__device__ int      g_col[EE];
__device__ float    g_dinv[NN];
__device__ unsigned g_state[512];            // lookback scan state
// bf16 hi/lo weights, [N][K] row-major (K contiguous)  == W^T
__device__ __nv_bfloat16 g_W1hi[128 * 128];
__device__ __nv_bfloat16 g_W1lo[128 * 128];
__device__ __nv_bfloat16 g_W2hi[64 * 128];
__device__ __nv_bfloat16 g_W2lo[64 * 128];

// ================= small helpers =================
__device__ __forceinline__ uint32_t smem_u32(const void* p) {
    uint32_t a;
    asm("{ .reg .u64 t; cvta.to.shared.u64 t, %1; cvt.u32.u64 %0, t; }" : "=r"(a) : "l"(p));
    return a;
}
__device__ __forceinline__ void ldmatrix_x4(uint32_t& r0, uint32_t& r1, uint32_t& r2,
                                            uint32_t& r3, uint32_t addr) {
    asm volatile("ldmatrix.sync.aligned.m8n8.x4.shared.b16 {%0,%1,%2,%3}, [%4];"
                 : "=r"(r0), "=r"(r1), "=r"(r2), "=r"(r3) : "r"(addr));
}
__device__ __forceinline__ void ldmatrix_x2(uint32_t& r0, uint32_t& r1, uint32_t addr) {
    asm volatile("ldmatrix.sync.aligned.m8n8.x2.shared.b16 {%0,%1}, [%2];"
                 : "=r"(r0), "=r"(r1) : "r"(addr));
}
__device__ __forceinline__ void mma_bf16(float* d, const uint32_t* a, const uint32_t* b) {
    asm volatile(
        "mma.sync.aligned.m16n8k16.row.col.f32.bf16.bf16.f32 "
        "{%0,%1,%2,%3}, {%4,%5,%6,%7}, {%8,%9}, {%0,%1,%2,%3};"
        : "+f"(d[0]), "+f"(d[1]), "+f"(d[2]), "+f"(d[3])
        : "r"(a[0]), "r"(a[1]), "r"(a[2]), "r"(a[3]), "r"(b[0]), "r"(b[1]));
}

// ======== weight convert (both layers in one kernel): fp32 [K][N] -> hi/lo bf16 [N][K] ========
__global__ void k_convW_all(const float* __restrict__ W1, const float* __restrict__ W2) {
    int i = blockIdx.x * blockDim.x + threadIdx.x;
    if (i < 128 * 128) {
        int k = i / 128, nn = i % 128;
        float v = W1[i];
        __nv_bfloat16 h = __float2bfloat16(v);
        g_W1hi[nn * 128 + k] = h;
        g_W1lo[nn * 128 + k] = __float2bfloat16(v - __bfloat162float(h));
    } else if (i < 128 * 128 + 128 * 64) {
        int j = i - 128 * 128;
        int k = j / 64, nn = j % 64;
        float v = W2[j];
        __nv_bfloat16 h = __float2bfloat16(v);
        g_W2hi[nn * 128 + k] = h;
        g_W2lo[nn * 128 + k] = __float2bfloat16(v - __bfloat162float(h));
    }
}

// ================= CSR build =================
// counts + zero the scan state (state used only by k_scan, launched after)
__global__ void k_count(const int* __restrict__ dst, int e) {
    int i = blockIdx.x * blockDim.x + threadIdx.x;
    if (i < 512) g_state[i] = 0u;
    if (i < e) atomicAdd(&g_cnt[dst[i]], 1);
}

// single-pass exclusive scan (decoupled lookback), also emits dinv and rowptr[n]
__global__ void k_scan(int n, int nb) {
    __shared__ int sh[512];
    __shared__ int s_prev;
    const int tid = threadIdx.x;
    const int b = blockIdx.x;
    const int i = b * 512 + tid;
    int v = (i < n) ? g_cnt[i] : 0;
    if (i < n) g_dinv[i] = rsqrtf((float)v + 1.0f);   // self-loop folded in
    sh[tid] = v;
    __syncthreads();
#pragma unroll
    for (int off = 1; off < 512; off <<= 1) {
        int t = (tid >= off) ? sh[tid - off] : 0;
        __syncthreads();
        sh[tid] += t;
        __syncthreads();
    }
    const int incl = sh[tid];
    const int total = sh[511];

    if (tid == 0) {
        if (b == 0) {
            atomicExch(&g_state[0], (2u << 30) | (unsigned)total);
            s_prev = 0;
        } else {
            atomicExch(&g_state[b], (1u << 30) | (unsigned)total);
            int run = 0, p = b - 1;
            while (true) {
                unsigned s;
                do { s = atomicOr(&g_state[p], 0u); } while ((s >> 30) == 0u);
                run += (int)(s & 0x3FFFFFFFu);
                if ((s >> 30) == 2u) break;
                p--;
            }
            atomicExch(&g_state[b], (2u << 30) | (unsigned)(run + total));
            s_prev = run;
        }
    }
    __syncthreads();
    const int base = s_prev;
    if (i < n) {
        int ex = base + incl - v;
        g_rowptr[i] = ex;
        g_wp[i] = ex;
    }
    if (b == nb - 1 && tid == 511) g_rowptr[n] = base + total;
}

__global__ void k_fill(const int* __restrict__ src, const int* __restrict__ dst, int e) {
    int i = blockIdx.x * blockDim.x + threadIdx.x;
    if (i < e) {
        int d = dst[i];
        int pos = atomicAdd(&g_wp[d], 1);
        g_col[pos] = src[i];
    }
}

// ================= mma.sync GEMM: G[r,:] = dinv[r] * (X[r,:128] @ W[:, :NCOL]) =================
// 3-term bf16 compensated: Ahi*Bhi + Ahi*Blo + Alo*Bhi, fp32 accumulate.
// CTA: 256 threads (8 warps), tile 128 x NCOL. Warp w: rows [w*16, w*16+16).
template <int NCOL>
__global__ void __launch_bounds__(256, 1)
k_gemm_mma(const float* __restrict__ X, const __nv_bfloat16* __restrict__ Bhi,
           const __nv_bfloat16* __restrict__ Blo, float* __restrict__ G, int n) {
    constexpr int K = 128;
    constexpr int PAD = 136;                 // halves per row (8 halves pad)
    constexpr int NT = NCOL / 8;             // n-tiles per warp
    constexpr int ABYTES = 128 * PAD * 2;    // 34816 per half
    constexpr int BBYTES = NCOL * PAD * 2;

    extern __shared__ char smem[];
    __nv_bfloat16* sAhi = (__nv_bfloat16*)(smem);
    __nv_bfloat16* sAlo = (__nv_bfloat16*)(smem + ABYTES);
    __nv_bfloat16* sBhi = (__nv_bfloat16*)(smem + 2 * ABYTES);
    __nv_bfloat16* sBlo = (__nv_bfloat16*)(smem + 2 * ABYTES + BBYTES);

    const int tid = threadIdx.x;
    const int wid = tid >> 5;
    const int lane = tid & 31;
    const int rowBase = blockIdx.x * 128;

    // ---- stage B (hi/lo) into padded smem, 16B chunks ----
    {
        const uint4* bh = (const uint4*)Bhi;
        const uint4* bl = (const uint4*)Blo;
        for (int c = tid; c < NCOL * 16; c += 256) {
            int r = c >> 4, c8 = c & 15;        // 8 halves per chunk
            uint4 vh = bh[c], vl = bl[c];
            *(uint4*)(&sBhi[r * PAD + c8 * 8]) = vh;
            *(uint4*)(&sBlo[r * PAD + c8 * 8]) = vl;
        }
    }

    // ---- stage A tile: 128 rows x 128 fp32 -> hi/lo bf16 ----
    for (int i = tid; i < 128 * 32; i += 256) {
        int r = i >> 5, c4 = i & 31;            // float4 index in row
        float4 v = make_float4(0.f, 0.f, 0.f, 0.f);
        int gr = rowBase + r;
        if (gr < n) v = ((const float4*)X)[(size_t)gr * 32 + c4];
        __nv_bfloat16 h0 = __float2bfloat16(v.x), h1 = __float2bfloat16(v.y);
        __nv_bfloat16 h2 = __float2bfloat16(v.z), h3 = __float2bfloat16(v.w);
        __nv_bfloat16 l0 = __float2bfloat16(v.x - __bfloat162float(h0));
        __nv_bfloat16 l1 = __float2bfloat16(v.y - __bfloat162float(h1));
        __nv_bfloat16 l2 = __float2bfloat16(v.z - __bfloat162float(h2));
        __nv_bfloat16 l3 = __float2bfloat16(v.w - __bfloat162float(h3));
        __nv_bfloat162* ph = (__nv_bfloat162*)&sAhi[r * PAD + c4 * 4];
        __nv_bfloat162* pl = (__nv_bfloat162*)&sAlo[r * PAD + c4 * 4];
        ph[0] = __nv_bfloat162(h0, h1); ph[1] = __nv_bfloat162(h2, h3);
        pl[0] = __nv_bfloat162(l0, l1); pl[1] = __nv_bfloat162(l2, l3);
    }
    __syncthreads();

    // ---- per-warp mma mainloop ----
    const int m0 = wid * 16;
    const uint32_t aRow = m0 + (lane & 15);
    const uint32_t aK = (lane >> 4) * 8;
    const uint32_t aHiAddr = smem_u32(&sAhi[aRow * PAD + aK]);
    const uint32_t aLoAddr = smem_u32(&sAlo[aRow * PAD + aK]);
    const uint32_t bRow = (lane & 7);
    const uint32_t bK = ((lane >> 3) & 1) * 8;
    const uint32_t bHiAddr = smem_u32(&sBhi[bRow * PAD + bK]);
    const uint32_t bLoAddr = smem_u32(&sBlo[bRow * PAD + bK]);

    float d[NT][4];
#pragma unroll
    for (int j = 0; j < NT; j++) { d[j][0] = 0.f; d[j][1] = 0.f; d[j][2] = 0.f; d[j][3] = 0.f; }

#pragma unroll
    for (int k0 = 0; k0 < K; k0 += 16) {
        uint32_t ahi[4], alo[4];
        ldmatrix_x4(ahi[0], ahi[1], ahi[2], ahi[3], aHiAddr + k0 * 2);
        ldmatrix_x4(alo[0], alo[1], alo[2], alo[3], aLoAddr + k0 * 2);
#pragma unroll
        for (int j = 0; j < NT; j++) {
            uint32_t bhi[2], blo[2];
            const uint32_t boff = (j * 8) * (PAD * 2) + k0 * 2;
            ldmatrix_x2(bhi[0], bhi[1], bHiAddr + boff);
            ldmatrix_x2(blo[0], blo[1], bLoAddr + boff);
            mma_bf16(d[j], ahi, bhi);
            mma_bf16(d[j], ahi, blo);
            mma_bf16(d[j], alo, bhi);
        }
    }

    // ---- epilogue: dinv row scale + store ----
    const int r0 = rowBase + m0 + (lane >> 2);
    const int r1 = r0 + 8;
    const int cbase = (lane & 3) * 2;
    const float s0 = (r0 < n) ? g_dinv[r0] : 0.f;
    const float s1 = (r1 < n) ? g_dinv[r1] : 0.f;
#pragma unroll
    for (int j = 0; j < NT; j++) {
        int col = j * 8 + cbase;
        if (r0 < n)
            *(float2*)(G + (size_t)r0 * NCOL + col) = make_float2(s0 * d[j][0], s0 * d[j][1]);
        if (r1 < n)
            *(float2*)(G + (size_t)r1 * NCOL + col) = make_float2(s1 * d[j][2], s1 * d[j][3]);
    }
}

// ================= aggregation: one warp per destination node =================
// out[d] = act( dinv[d] * (sum_{s in N(d)} G[s] + G[d]) + bias )   (G pre-scaled by dinv[src])
template <int D, bool LAYER2>
__global__ void k_agg(const float* __restrict__ G, const float* __restrict__ bias,
                      float* __restrict__ out, int n) {
    const int warp = (blockIdx.x * blockDim.x + threadIdx.x) >> 5;
    const int lane = threadIdx.x & 31;
    if (warp >= n) return;
    constexpr int VPL = D / 32;

    float acc[VPL];
    {
        const float* row = G + (size_t)warp * D;
        if (VPL == 4) {
            float4 v = ((const float4*)row)[lane];
            acc[0] = v.x; acc[1] = v.y; acc[2] = v.z; acc[3] = v.w;
        } else {
            float2 v = ((const float2*)row)[lane];
            acc[0] = v.x; acc[1] = v.y;
        }
    }

    int r = g_rowptr[warp];
    const int end = g_rowptr[warp + 1];

    // unroll-4 for memory-level parallelism
    for (; r + 3 < end; r += 4) {
        int s0 = g_col[r], s1 = g_col[r + 1], s2 = g_col[r + 2], s3 = g_col[r + 3];
        if (VPL == 4) {
            float4 v0 = ((const float4*)(G + (size_t)s0 * D))[lane];
            float4 v1 = ((const float4*)(G + (size_t)s1 * D))[lane];
            float4 v2 = ((const float4*)(G + (size_t)s2 * D))[lane];
            float4 v3 = ((const float4*)(G + (size_t)s3 * D))[lane];
            acc[0] += v0.x + v1.x + v2.x + v3.x;
            acc[1] += v0.y + v1.y + v2.y + v3.y;
            acc[2] += v0.z + v1.z + v2.z + v3.z;
            acc[3] += v0.w + v1.w + v2.w + v3.w;
        } else {
            float2 v0 = ((const float2*)(G + (size_t)s0 * D))[lane];
            float2 v1 = ((const float2*)(G + (size_t)s1 * D))[lane];
            float2 v2 = ((const float2*)(G + (size_t)s2 * D))[lane];
            float2 v3 = ((const float2*)(G + (size_t)s3 * D))[lane];
            acc[0] += v0.x + v1.x + v2.x + v3.x;
            acc[1] += v0.y + v1.y + v2.y + v3.y;
        }
    }
    for (; r < end; r++) {
        int s = g_col[r];
        if (VPL == 4) {
            float4 v = ((const float4*)(G + (size_t)s * D))[lane];
            acc[0] += v.x; acc[1] += v.y; acc[2] += v.z; acc[3] += v.w;
        } else {
            float2 v = ((const float2*)(G + (size_t)s * D))[lane];
            acc[0] += v.x; acc[1] += v.y;
        }
    }

    const float dv = g_dinv[warp];

    if (!LAYER2) {
        const float alpha = 1.6732632423543772f;
        const float scale = 1.0507009873554805f;
        float o[VPL];
#pragma unroll
        for (int v = 0; v < VPL; v++) {
            float x = dv * acc[v] + bias[lane * VPL + v];
            o[v] = scale * (x > 0.f ? x : alpha * (expf(x) - 1.f));
        }
        if (VPL == 4) {
            ((float4*)(out + (size_t)warp * D))[lane] = make_float4(o[0], o[1], o[2], o[3]);
        }
    } else {
        float v0 = dv * acc[0] + bias[lane * 2];
        float v1 = dv * acc[1] + bias[lane * 2 + 1];
        float m = fmaxf(v0, v1);
#pragma unroll
        for (int o = 16; o >= 1; o >>= 1) m = fmaxf(m, __shfl_xor_sync(0xffffffffu, m, o));
        float s = expf(v0 - m) + expf(v1 - m);
#pragma unroll
        for (int o = 16; o >= 1; o >>= 1) s += __shfl_xor_sync(0xffffffffu, s, o);
        float l = logf(s);
        ((float2*)(out + (size_t)warp * D))[lane] = make_float2(v0 - m - l, v1 - m - l);
    }
}

// ================= launch =================
extern "C" void kernel_launch(void* const* d_in, const int* in_sizes, int n_in,
                              void* d_out, int out_size) {
    const float* x  = (const float*)d_in[0];
    const int*   ei = (const int*)d_in[1];
    const float* W1 = (const float*)d_in[2];
    const float* b1 = (const float*)d_in[3];
    const float* W2 = (const float*)d_in[4];
    const float* b2 = (const float*)d_in[5];
    float* out = (float*)d_out;

    const int n = in_sizes[0] / KDIM;   // 100000
    const int e = in_sizes[1] / 2;      // 1600000
    const int* src = ei;
    const int* dst = ei + e;

    float *pA, *pB;
    int* pCnt;
    __nv_bfloat16 *w1h, *w1l, *w2h, *w2l;
    cudaGetSymbolAddress((void**)&pA, g_bufA);
    cudaGetSymbolAddress((void**)&pB, g_bufB);
    cudaGetSymbolAddress((void**)&pCnt, g_cnt);
    cudaGetSymbolAddress((void**)&w1h, g_W1hi);
    cudaGetSymbolAddress((void**)&w1l, g_W1lo);
    cudaGetSymbolAddress((void**)&w2h, g_W2hi);
    cudaGetSymbolAddress((void**)&w2l, g_W2lo);

    const int nb = (n + 511) / 512;     // 196 blocks, all co-resident (lookback safe)

    // 1) weights (independent of CSR)
    k_convW_all<<<(128 * 128 + 128 * 64 + 255) / 256, 256>>>(W1, W2);

    // 2) CSR + dinv (memset node + 3 kernels)
    cudaMemsetAsync(pCnt, 0, (size_t)n * sizeof(int));
    k_count<<<(e + 255) / 256, 256>>>(dst, e);
    k_scan<<<nb, 512>>>(n, nb);
    k_fill<<<(e + 255) / 256, 256>>>(src, dst, e);

    // 3) GEMMs + aggregations
    constexpr int SM1 = 2 * (128 * 136 * 2) + 2 * (128 * 136 * 2);  // 139264
    constexpr int SM2 = 2 * (128 * 136 * 2) + 2 * (64 * 136 * 2);   // 104448
    cudaFuncSetAttribute(k_gemm_mma<128>, cudaFuncAttributeMaxDynamicSharedMemorySize, SM1);
    cudaFuncSetAttribute(k_gemm_mma<64>,  cudaFuncAttributeMaxDynamicSharedMemorySize, SM2);

    const int gemm_grid = (n + 127) / 128;   // 782
    const int agg_grid = (n * 32 + 255) / 256;

    k_gemm_mma<128><<<gemm_grid, 256, SM1>>>(x, w1h, w1l, pA, n);
    k_agg<128, false><<<agg_grid, 256>>>(pA, b1, pB, n);
    k_gemm_mma<64><<<gemm_grid, 256, SM2>>>(pB, w2h, w2l, pA, n);
    k_agg<64, true><<<agg_grid, 256>>>(pA, b2, out, n);
}